// round 4
// baseline (speedup 1.0000x reference)
#include <cuda_runtime.h>
#include <math.h>

// Problem constants
#define NN 9216      // H*W = 96*96
#define CC 64        // channels
#define C8 8         // C/8
#define BB 2         // batch

// -------- scratch (static device globals: no runtime allocation) ----------
__device__ float d_invsig[3];                       // 1/sigma for Wq, Wk, Wv
__device__ float d_f[BB * NN * C8];                 // raw keys   f~[b][i][c8]  (Wq x, no bias/scale)
__device__ float d_g[BB * NN * C8];                 // raw queries g~[b][j][c8] (Wk x)
__device__ float d_h[BB * NN * CC];                 // raw values h~[b][i][c]   (Wv x)

// ---------------- packed fp32x2 helpers (SASS FFMA2 path) -----------------
__device__ __forceinline__ unsigned long long pk2(float a, float b) {
    unsigned long long r;
    asm("mov.b64 %0, {%1, %2};" : "=l"(r) : "f"(a), "f"(b));
    return r;
}
__device__ __forceinline__ void fma2(unsigned long long& d,
                                     unsigned long long a, unsigned long long b) {
    asm("fma.rn.f32x2 %0, %1, %2, %0;" : "+l"(d) : "l"(a), "l"(b));
}
__device__ __forceinline__ float2 upk2(unsigned long long v) {
    float2 f;
    asm("mov.b64 {%0, %1}, %2;" : "=f"(f.x), "=f"(f.y) : "l"(v));
    return f;
}

// ===========================================================================
// K1 (merged): blocks 0-2 do spectral power iteration (shuffle-reduced);
// blocks 3-74 compute RAW projections f~=Wq x, g~=Wk x, h~=Wv x.
// The two halves are independent -> they run concurrently in one launch.
// Normalization scales + biases are applied later in attn staging.
// ===========================================================================
__global__ void __launch_bounds__(256) prep_kernel(
        const float* __restrict__ x,
        const float* __restrict__ Wq,
        const float* __restrict__ Wk,
        const float* __restrict__ Wv) {
    __shared__ float shb[8448];
    int t = threadIdx.x;

    if (blockIdx.x < 3) {
        // ---------------- spectral norm: sigma = sqrt(lambda_max(W W^T)) ----
        int mat = blockIdx.x;
        const float* W = (mat == 0) ? Wq : (mat == 1) ? Wk : Wv;
        int dim = (mat == 2) ? 64 : 8;
        float* Wsh  = shb;              // 4096
        float* G    = shb + 4096;       // 64*65 padded
        float* vv   = shb + 8256;       // 64
        float* part = shb + 8320;       // 8

        for (int i = t; i < dim * 64; i += 256) Wsh[i] = W[i];
        if (t < 8) part[t] = 0.f;
        __syncthreads();

        if (t < dim) {
            float wr[64];
#pragma unroll
            for (int c = 0; c < 64; c++) wr[c] = Wsh[t * 64 + c];
            for (int j = 0; j < dim; j++) {
                float s = 0.f;
                for (int c = 0; c < 64; c++) s += wr[c] * Wsh[j * 64 + c];
                G[t * 65 + j] = s;
            }
            vv[t] = 1.f;
        }
        __syncthreads();

        float tot = 0.f;
        for (int it = 0; it < 250; it++) {
            float w = 0.f;
            if (t < dim) {
                float a0 = 0.f, a1 = 0.f, a2 = 0.f, a3 = 0.f;
                const float* gr = G + t * 65;
                for (int j = 0; j < dim; j += 4) {
                    a0 += gr[j + 0] * vv[j + 0];
                    a1 += gr[j + 1] * vv[j + 1];
                    a2 += gr[j + 2] * vv[j + 2];
                    a3 += gr[j + 3] * vv[j + 3];
                }
                w = (a0 + a1) + (a2 + a3);
            }
            float sq = w * w;
#pragma unroll
            for (int o = 16; o > 0; o >>= 1)
                sq += __shfl_xor_sync(0xffffffffu, sq, o);
            if ((t & 31) == 0) part[t >> 5] = sq;
            __syncthreads();
            tot = part[0] + part[1];
            float rinv = 1.f / sqrtf(tot);
            if (t < dim) vv[t] = w * rinv;
            __syncthreads();
        }
        // lambda = ||G v|| -> sigma = sqrt(lambda); invsig = 1/sigma
        if (t == 0) d_invsig[mat] = 1.f / sqrtf(sqrtf(tot));
    } else {
        // ---------------- raw projections ----------------
        float* wq = shb;            // 512
        float* wk = shb + 512;      // 512
        float* wv = shb + 1024;     // 4096

        for (int i = t; i < 512; i += 256) { wq[i] = Wq[i]; wk[i] = Wk[i]; }
        for (int i = t; i < 4096; i += 256) wv[i] = Wv[i];
        __syncthreads();

        int gid = (blockIdx.x - 3) * 256 + t;       // 0 .. 18431
        int b = gid / NN, n = gid % NN;

        float fa[8] = {0.f}, ga[8] = {0.f}, ha[64] = {0.f};
        const float* xp = x + (size_t)b * CC * NN + n;
        for (int c = 0; c < 64; c++) {
            float xc = xp[(size_t)c * NN];
#pragma unroll
            for (int o = 0; o < 8; o++) {
                fa[o] += wq[o * 64 + c] * xc;
                ga[o] += wk[o * 64 + c] * xc;
            }
#pragma unroll
            for (int o = 0; o < 64; o++) ha[o] += wv[o * 64 + c] * xc;
        }

        size_t b8 = ((size_t)b * NN + n) * 8;
#pragma unroll
        for (int o = 0; o < 8; o++) { d_f[b8 + o] = fa[o]; d_g[b8 + o] = ga[o]; }
        size_t b64 = ((size_t)b * NN + n) * 64;
#pragma unroll
        for (int o = 0; o < 64; o++) d_h[b64 + o] = ha[o];
    }
}

// ===========================================================================
// K2: two-pass tiled attention. Scale (1/sigma) + bias applied at staging.
//   Pass 1: exact max m_j over keys (packed-score sweep).
//   Pass 2: P = exp(S - m); O += H @ P via packed FFMA2; l += colsum(P).
//   Epilogue: out = gamma * O / l + x.
// Thread layout: 256 = 16(ty: c) x 16(tx: q); each thread owns a 4x4 O tile.
// ===========================================================================
__global__ void __launch_bounds__(256, 2) attn_kernel(
        const float* __restrict__ x,
        const float* __restrict__ bq,
        const float* __restrict__ bk,
        const float* __restrict__ bv,
        const float* __restrict__ gamma,
        float* __restrict__ out) {
    __shared__ __align__(16) float h_sh[64 * 64];   // [k][c]
    __shared__ __align__(16) float p_sh[64 * 68];   // [k][q], padded
    __shared__ float f_sh[64 * 9];                  // [k][d], padded
    __shared__ float g_sh[64 * 9];                  // [q][d], padded
    __shared__ float red[16 * 64];
    __shared__ float m_sh[64];
    __shared__ float l_sh[64];

    int t  = threadIdx.x;
    int tx = t & 15;        // query group
    int ty = t >> 4;        // channel / key group
    int b  = blockIdx.y;
    int qt = blockIdx.x;

    float iq = d_invsig[0], ik = d_invsig[1], iv = d_invsig[2];

    // stage g tile once (normalized + bias)
    const float* gp = d_g + ((size_t)b * NN + qt * 64) * 8;
    for (int i = t; i < 512; i += 256)
        g_sh[(i >> 3) * 9 + (i & 7)] = ik * gp[i] + bk[i & 7];
    __syncthreads();

    // this thread's 4 query vectors, packed as 2 q-pairs
    unsigned long long gq2[2][8];
#pragma unroll
    for (int p = 0; p < 2; p++)
#pragma unroll
        for (int d = 0; d < 8; d++)
            gq2[p][d] = pk2(g_sh[(tx * 4 + 2 * p) * 9 + d],
                            g_sh[(tx * 4 + 2 * p + 1) * 9 + d]);

    // ---------------- pass 1: exact max over keys ----------------
    float mloc[4] = {-1e30f, -1e30f, -1e30f, -1e30f};
    for (int kt = 0; kt < NN / 64; kt++) {
        const float* fp = d_f + ((size_t)b * NN + kt * 64) * 8;
        for (int i = t; i < 512; i += 256)
            f_sh[(i >> 3) * 9 + (i & 7)] = iq * fp[i] + bq[i & 7];
        __syncthreads();
#pragma unroll
        for (int kk = 0; kk < 4; kk++) {
            int k = ty * 4 + kk;
            unsigned long long fk2[8];
#pragma unroll
            for (int d = 0; d < 8; d++) {
                float fv = f_sh[k * 9 + d];
                fk2[d] = pk2(fv, fv);
            }
            unsigned long long s0 = 0ull, s1 = 0ull;
#pragma unroll
            for (int d = 0; d < 8; d++) {
                fma2(s0, fk2[d], gq2[0][d]);
                fma2(s1, fk2[d], gq2[1][d]);
            }
            float2 sa = upk2(s0), sb = upk2(s1);
            mloc[0] = fmaxf(mloc[0], sa.x);
            mloc[1] = fmaxf(mloc[1], sa.y);
            mloc[2] = fmaxf(mloc[2], sb.x);
            mloc[3] = fmaxf(mloc[3], sb.y);
        }
        __syncthreads();
    }
#pragma unroll
    for (int qq = 0; qq < 4; qq++) red[ty * 64 + tx * 4 + qq] = mloc[qq];
    __syncthreads();
    if (t < 64) {
        float mm = -1e30f;
        for (int r = 0; r < 16; r++) mm = fmaxf(mm, red[r * 64 + t]);
        m_sh[t] = mm;
    }
    __syncthreads();
    float mq[4];
#pragma unroll
    for (int qq = 0; qq < 4; qq++) mq[qq] = m_sh[tx * 4 + qq];

    // ---------------- pass 2: exp + PV GEMM (FFMA2) + denominator ----------
    unsigned long long A[4][2];   // [q][c-pair]: (c0,c1) and (c2,c3)
#pragma unroll
    for (int j = 0; j < 4; j++) { A[j][0] = 0ull; A[j][1] = 0ull; }
    float lloc[4] = {0.f, 0.f, 0.f, 0.f};

    const float4* bv4 = (const float4*)bv;

    for (int kt = 0; kt < NN / 64; kt++) {
        const float* fp = d_f + ((size_t)b * NN + kt * 64) * 8;
        const float* hp = d_h + ((size_t)b * NN + kt * 64) * 64;
        for (int i = t; i < 512; i += 256)
            f_sh[(i >> 3) * 9 + (i & 7)] = iq * fp[i] + bq[i & 7];
        for (int i = t; i < 1024; i += 256) {
            float4 hv = ((const float4*)hp)[i];
            float4 bb = bv4[i & 15];
            hv.x = iv * hv.x + bb.x;
            hv.y = iv * hv.y + bb.y;
            hv.z = iv * hv.z + bb.z;
            hv.w = iv * hv.w + bb.w;
            ((float4*)h_sh)[i] = hv;
        }
        __syncthreads();

        // scores (packed) + exp -> p_sh, partial l
#pragma unroll
        for (int kk = 0; kk < 4; kk++) {
            int k = ty * 4 + kk;
            unsigned long long fk2[8];
#pragma unroll
            for (int d = 0; d < 8; d++) {
                float fv = f_sh[k * 9 + d];
                fk2[d] = pk2(fv, fv);
            }
            unsigned long long s0 = 0ull, s1 = 0ull;
#pragma unroll
            for (int d = 0; d < 8; d++) {
                fma2(s0, fk2[d], gq2[0][d]);
                fma2(s1, fk2[d], gq2[1][d]);
            }
            float2 sa = upk2(s0), sb = upk2(s1);
            float p0 = __expf(sa.x - mq[0]);
            float p1 = __expf(sa.y - mq[1]);
            float p2 = __expf(sb.x - mq[2]);
            float p3 = __expf(sb.y - mq[3]);
            lloc[0] += p0; lloc[1] += p1; lloc[2] += p2; lloc[3] += p3;
            p_sh[k * 68 + tx * 4 + 0] = p0;
            p_sh[k * 68 + tx * 4 + 1] = p1;
            p_sh[k * 68 + tx * 4 + 2] = p2;
            p_sh[k * 68 + tx * 4 + 3] = p3;
        }
        __syncthreads();

        // O[64x64] += H^T @ P, packed along the c dimension
#pragma unroll 4
        for (int k = 0; k < 64; k++) {
            float4 hv = *(const float4*)(h_sh + k * 64 + ty * 4);
            float4 pv = *(const float4*)(p_sh + k * 68 + tx * 4);
            unsigned long long h01 = pk2(hv.x, hv.y);
            unsigned long long h23 = pk2(hv.z, hv.w);
            unsigned long long p0 = pk2(pv.x, pv.x);
            unsigned long long p1 = pk2(pv.y, pv.y);
            unsigned long long p2 = pk2(pv.z, pv.z);
            unsigned long long p3 = pk2(pv.w, pv.w);
            fma2(A[0][0], h01, p0); fma2(A[0][1], h23, p0);
            fma2(A[1][0], h01, p1); fma2(A[1][1], h23, p1);
            fma2(A[2][0], h01, p2); fma2(A[2][1], h23, p2);
            fma2(A[3][0], h01, p3); fma2(A[3][1], h23, p3);
        }
        __syncthreads();
    }

    // reduce denominator l across ty groups
#pragma unroll
    for (int qq = 0; qq < 4; qq++) red[ty * 64 + tx * 4 + qq] = lloc[qq];
    __syncthreads();
    if (t < 64) {
        float s = 0.f;
        for (int r = 0; r < 16; r++) s += red[r * 64 + t];
        l_sh[t] = s;
    }
    __syncthreads();

    float gam = gamma[0];
    float linv[4];
#pragma unroll
    for (int qq = 0; qq < 4; qq++) linv[qq] = 1.f / l_sh[tx * 4 + qq];

    // unpack accumulators: acc_s[c][q]
    float acc_s[4][4];
#pragma unroll
    for (int j = 0; j < 4; j++) {
        float2 lo = upk2(A[j][0]);
        float2 hi = upk2(A[j][1]);
        acc_s[0][j] = lo.x;
        acc_s[1][j] = lo.y;
        acc_s[2][j] = hi.x;
        acc_s[3][j] = hi.y;
    }

#pragma unroll
    for (int cc = 0; cc < 4; cc++) {
        int c = ty * 4 + cc;
        size_t base = ((size_t)b * CC + c) * NN + qt * 64 + tx * 4;
        float4 xin = *(const float4*)(x + base);
        float4 r;
        r.x = gam * acc_s[cc][0] * linv[0] + xin.x;
        r.y = gam * acc_s[cc][1] * linv[1] + xin.y;
        r.z = gam * acc_s[cc][2] * linv[2] + xin.z;
        r.w = gam * acc_s[cc][3] * linv[3] + xin.w;
        *(float4*)(out + base) = r;
    }
}

// ===========================================================================
extern "C" void kernel_launch(void* const* d_in, const int* in_sizes, int n_in,
                              void* d_out, int out_size) {
    const float* x     = (const float*)d_in[0];
    const float* Wq    = (const float*)d_in[1];
    const float* bq    = (const float*)d_in[2];
    const float* Wk    = (const float*)d_in[3];
    const float* bk    = (const float*)d_in[4];
    const float* Wv    = (const float*)d_in[5];
    const float* bv    = (const float*)d_in[6];
    const float* gamma = (const float*)d_in[7];
    float* out = (float*)d_out;

    prep_kernel<<<3 + (BB * NN) / 256, 256>>>(x, Wq, Wk, Wv);
    attn_kernel<<<dim3(NN / 64, BB), 256>>>(x, bq, bk, bv, gamma, out);
}

// round 5
// speedup vs baseline: 1.5542x; 1.5542x over previous
#include <cuda_runtime.h>
#include <math.h>

// Problem constants
#define NN 9216      // H*W = 96*96
#define CC 64        // channels
#define C8 8         // C/8
#define BB 2         // batch

// -------- scratch (static device globals: no runtime allocation) ----------
__device__ float d_invsig[3];                       // 1/sigma for Wq, Wk, Wv
__device__ float d_f[BB * NN * C8];                 // raw keys    f~ = Wq x
__device__ float d_g[BB * NN * C8];                 // raw queries g~ = Wk x
__device__ float d_h[BB * NN * CC];                 // raw values  h~ = Wv x

// ===========================================================================
// K1 (merged): blocks 0-2 spectral norm (squaring + short power iteration);
// blocks 3-74 raw projections. Independent halves run concurrently.
// ===========================================================================
#define SQ_ITERS 4
#define PW_ITERS 16

__global__ void __launch_bounds__(256) prep_kernel(
        const float* __restrict__ x,
        const float* __restrict__ Wq,
        const float* __restrict__ Wk,
        const float* __restrict__ Wv) {
    __shared__ float shb[8704];
    __shared__ float part[8];
    __shared__ float scal;
    int t = threadIdx.x;

    if (blockIdx.x < 3) {
        // ---- sigma = sqrt(lambda_max(W W^T)) via squaring + power iter ----
        int mat = blockIdx.x;
        const float* W = (mat == 0) ? Wq : (mat == 1) ? Wk : Wv;
        int dim = (mat == 2) ? 64 : 8;
        float* Ga = shb;                 // 64*65
        float* Gb = shb + 4160;          // 64*65 (also W staging)
        float* vv = shb + 8320;          // 64
        float* ww = shb + 8384;          // 64

        // stage W (padded rows of 65) into Gb
        for (int i = t; i < dim * 64; i += 256)
            Gb[(i >> 6) * 65 + (i & 63)] = W[i];
        __syncthreads();

        // G = W W^T  -> Ga
        if (dim == 64) {
            int r = t >> 2, c0 = (t & 3) << 4;
            float rr[64];
#pragma unroll
            for (int j = 0; j < 64; j++) rr[j] = Gb[r * 65 + j];
            float acc[16];
#pragma unroll
            for (int cc = 0; cc < 16; cc++) acc[cc] = 0.f;
            for (int j = 0; j < 64; j++)
#pragma unroll
                for (int cc = 0; cc < 16; cc++)
                    acc[cc] += rr[j] * Gb[(c0 + cc) * 65 + j];
#pragma unroll
            for (int cc = 0; cc < 16; cc++) Ga[r * 65 + c0 + cc] = acc[cc];
        } else if (t < 64) {
            int r = t >> 3, c = t & 7;
            float s = 0.f;
            for (int j = 0; j < 64; j++) s += Gb[r * 65 + j] * Gb[c * 65 + j];
            Ga[r * 65 + c] = s;
        }
        __syncthreads();

        // normalized squarings; track l0 = log2(lam)/2^S + sum log2(f_j)/2^j
        float logl = 0.f, pw = 1.f;
        float* src = Ga;
        float* dst = Gb;
        for (int it = 0; it < SQ_ITERS; it++) {
            // Frobenius norm of src
            float ss = 0.f;
            for (int e = t; e < dim * dim; e += 256) {
                float v = src[(e / dim) * 65 + (e % dim)];
                ss += v * v;
            }
#pragma unroll
            for (int o = 16; o > 0; o >>= 1)
                ss += __shfl_xor_sync(0xffffffffu, ss, o);
            if ((t & 31) == 0) part[t >> 5] = ss;
            __syncthreads();
            float tot = 0.f;
#pragma unroll
            for (int i = 0; i < 8; i++) tot += part[i];
            float fro = sqrtf(tot);
            float inv2 = 1.f / tot;              // (1/fro)^2
            logl += log2f(fro) * pw;
            pw *= 0.5f;

            // dst = (src/fro)^2
            if (dim == 64) {
                int r = t >> 2, c0 = (t & 3) << 4;
                float rr[64];
#pragma unroll
                for (int j = 0; j < 64; j++) rr[j] = src[r * 65 + j];
                float acc[16];
#pragma unroll
                for (int cc = 0; cc < 16; cc++) acc[cc] = 0.f;
                for (int j = 0; j < 64; j++)
#pragma unroll
                    for (int cc = 0; cc < 16; cc++)
                        acc[cc] += rr[j] * src[j * 65 + c0 + cc];
#pragma unroll
                for (int cc = 0; cc < 16; cc++)
                    dst[r * 65 + c0 + cc] = acc[cc] * inv2;
            } else if (t < 64) {
                int r = t >> 3, c = t & 7;
                float s = 0.f;
#pragma unroll
                for (int j = 0; j < 8; j++) s += src[r * 65 + j] * src[j * 65 + c];
                dst[r * 65 + c] = s * inv2;
            }
            __syncthreads();
            float* tmp = src; src = dst; dst = tmp;
        }

        // short power iteration on src for lam = lambda_max(G_S)
        if (t < dim) vv[t] = 1.f;
        __syncthreads();
        float lam = 1.f;
        for (int it = 0; it < PW_ITERS; it++) {
            float w = 0.f;
            if (t < dim) {
                const float* gr = src + t * 65;
                for (int j = 0; j < dim; j++) w += gr[j] * vv[j];
            }
            float sq = w * w;
#pragma unroll
            for (int o = 16; o > 0; o >>= 1)
                sq += __shfl_xor_sync(0xffffffffu, sq, o);
            if ((t & 31) == 0) part[t >> 5] = sq;
            __syncthreads();
            if (t == 0) scal = sqrtf(part[0] + part[1]);
            __syncthreads();
            lam = scal;
            if (t < dim) vv[t] = w / lam;
            __syncthreads();
        }
        // invsig = lambda_max(G0)^(-1/4)... sigma = sqrt(lam0); lam0 = 2^l0
        if (t == 0) {
            float l0 = log2f(lam) * pw + logl;
            d_invsig[mat] = exp2f(-0.5f * l0);
        }
        (void)ww;
    } else {
        // ---------------- raw projections ----------------
        float* wq = shb;            // 512
        float* wk = shb + 512;      // 512
        float* wv = shb + 1024;     // 4096

        for (int i = t; i < 512; i += 256) { wq[i] = Wq[i]; wk[i] = Wk[i]; }
        for (int i = t; i < 4096; i += 256) wv[i] = Wv[i];
        __syncthreads();

        int gid = (blockIdx.x - 3) * 256 + t;       // 0 .. 18431
        int b = gid / NN, n = gid % NN;

        float fa[8] = {0.f}, ga[8] = {0.f}, ha[64] = {0.f};
        const float* xp = x + (size_t)b * CC * NN + n;
        for (int c = 0; c < 64; c++) {
            float xc = xp[(size_t)c * NN];
#pragma unroll
            for (int o = 0; o < 8; o++) {
                fa[o] += wq[o * 64 + c] * xc;
                ga[o] += wk[o * 64 + c] * xc;
            }
#pragma unroll
            for (int o = 0; o < 64; o++) ha[o] += wv[o * 64 + c] * xc;
        }

        size_t b8 = ((size_t)b * NN + n) * 8;
#pragma unroll
        for (int o = 0; o < 8; o++) { d_f[b8 + o] = fa[o]; d_g[b8 + o] = ga[o]; }
        size_t b64 = ((size_t)b * NN + n) * 64;
#pragma unroll
        for (int o = 0; o < 64; o++) d_h[b64 + o] = ha[o];
    }
}

// ===========================================================================
// K2: two-pass tiled attention, scale+bias fused at staging.
//   Pass 1: exact max via direct-L2 f sweep (no smem, no syncs).
//   Pass 2: per 64-key tile: stage f,h -> P=exp(S-m) -> O += H @ P, l += sum.
//   Epilogue: out = gamma * O / l + x.
// 256 threads = 16(ty: c/key) x 16(tx: q); 4x4 register tile per thread.
// ===========================================================================
__global__ void __launch_bounds__(256, 2) attn_kernel(
        const float* __restrict__ x,
        const float* __restrict__ bq,
        const float* __restrict__ bk,
        const float* __restrict__ bv,
        const float* __restrict__ gamma,
        float* __restrict__ out) {
    __shared__ __align__(16) float h_sh[64 * 64];   // [k][c]
    __shared__ __align__(16) float p_sh[64 * 68];   // [k][q], padded
    __shared__ float f_sh[64 * 9];                  // [k][d], padded
    __shared__ float g_sh[64 * 9];                  // [q][d], padded
    __shared__ float red[16 * 64];
    __shared__ float m_sh[64];
    __shared__ float l_sh[64];

    int t  = threadIdx.x;
    int tx = t & 15;        // query group
    int ty = t >> 4;        // channel / key group
    int b  = blockIdx.y;
    int qt = blockIdx.x;

    float iq = d_invsig[0], ik = d_invsig[1], iv = d_invsig[2];

    // stage g tile once (fully scaled + bias)
    const float* gp = d_g + ((size_t)b * NN + qt * 64) * 8;
    for (int i = t; i < 512; i += 256)
        g_sh[(i >> 3) * 9 + (i & 7)] = ik * gp[i] + __ldg(bk + (i & 7));
    __syncthreads();

    // this thread's 4 query vectors + bq-dot constants
    float gq[4][8], cq[4];
#pragma unroll
    for (int qq = 0; qq < 4; qq++) {
        float c = 0.f;
#pragma unroll
        for (int d = 0; d < 8; d++) {
            gq[qq][d] = g_sh[(tx * 4 + qq) * 9 + d];
            c += __ldg(bq + d) * gq[qq][d];
        }
        cq[qq] = c;
    }

    // ---------------- pass 1: exact max, raw f straight from L2 ----------
    // s = iq * (f_raw . g) + (bq . g)   (shift-exactness not required)
    float mloc[4] = {-1e30f, -1e30f, -1e30f, -1e30f};
    {
        const float4* fb = (const float4*)(d_f + (size_t)b * NN * 8);
        for (int k = ty * 2; k < NN; k += 32) {
            float4 a0 = __ldg(fb + k * 2);
            float4 a1 = __ldg(fb + k * 2 + 1);
            float4 a2 = __ldg(fb + k * 2 + 2);
            float4 a3 = __ldg(fb + k * 2 + 3);
#pragma unroll
            for (int qq = 0; qq < 4; qq++) {
                float s0 = a0.x * gq[qq][0] + a0.y * gq[qq][1]
                         + a0.z * gq[qq][2] + a0.w * gq[qq][3]
                         + a1.x * gq[qq][4] + a1.y * gq[qq][5]
                         + a1.z * gq[qq][6] + a1.w * gq[qq][7];
                float s1 = a2.x * gq[qq][0] + a2.y * gq[qq][1]
                         + a2.z * gq[qq][2] + a2.w * gq[qq][3]
                         + a3.x * gq[qq][4] + a3.y * gq[qq][5]
                         + a3.z * gq[qq][6] + a3.w * gq[qq][7];
                mloc[qq] = fmaxf(mloc[qq],
                                 fmaxf(iq * s0 + cq[qq], iq * s1 + cq[qq]));
            }
        }
    }
#pragma unroll
    for (int qq = 0; qq < 4; qq++) red[ty * 64 + tx * 4 + qq] = mloc[qq];
    __syncthreads();
    if (t < 64) {
        float mm = -1e30f;
        for (int r = 0; r < 16; r++) mm = fmaxf(mm, red[r * 64 + t]);
        m_sh[t] = mm;
    }
    __syncthreads();
    float mq[4];
#pragma unroll
    for (int qq = 0; qq < 4; qq++) mq[qq] = m_sh[tx * 4 + qq];

    // ---------------- pass 2: exp + PV GEMM + denominator ----------------
    float acc[4][4];
#pragma unroll
    for (int i = 0; i < 4; i++)
#pragma unroll
        for (int j = 0; j < 4; j++) acc[i][j] = 0.f;
    float lloc[4] = {0.f, 0.f, 0.f, 0.f};

    const float4* bv4 = (const float4*)bv;

    for (int kt = 0; kt < NN / 64; kt++) {
        const float* fp = d_f + ((size_t)b * NN + kt * 64) * 8;
        const float* hp = d_h + ((size_t)b * NN + kt * 64) * 64;
        for (int i = t; i < 512; i += 256)
            f_sh[(i >> 3) * 9 + (i & 7)] = iq * fp[i] + __ldg(bq + (i & 7));
        for (int i = t; i < 1024; i += 256) {
            float4 hv = ((const float4*)hp)[i];
            float4 bb = bv4[i & 15];
            hv.x = iv * hv.x + bb.x;
            hv.y = iv * hv.y + bb.y;
            hv.z = iv * hv.z + bb.z;
            hv.w = iv * hv.w + bb.w;
            ((float4*)h_sh)[i] = hv;
        }
        __syncthreads();

        // scores + exp -> p_sh, partial l
#pragma unroll
        for (int kk = 0; kk < 4; kk++) {
            int k = ty * 4 + kk;
            float fk[8];
#pragma unroll
            for (int d = 0; d < 8; d++) fk[d] = f_sh[k * 9 + d];
#pragma unroll
            for (int qq = 0; qq < 4; qq++) {
                float s = 0.f;
#pragma unroll
                for (int d = 0; d < 8; d++) s += fk[d] * gq[qq][d];
                float p = __expf(s - mq[qq]);
                lloc[qq] += p;
                p_sh[k * 68 + tx * 4 + qq] = p;
            }
        }
        __syncthreads();

        // O[64x64] += H^T-view @ P  (k contraction)
#pragma unroll 4
        for (int k = 0; k < 64; k++) {
            float4 hv = *(const float4*)(h_sh + k * 64 + ty * 4);
            float4 pv = *(const float4*)(p_sh + k * 68 + tx * 4);
            acc[0][0] += hv.x * pv.x; acc[0][1] += hv.x * pv.y;
            acc[0][2] += hv.x * pv.z; acc[0][3] += hv.x * pv.w;
            acc[1][0] += hv.y * pv.x; acc[1][1] += hv.y * pv.y;
            acc[1][2] += hv.y * pv.z; acc[1][3] += hv.y * pv.w;
            acc[2][0] += hv.z * pv.x; acc[2][1] += hv.z * pv.y;
            acc[2][2] += hv.z * pv.z; acc[2][3] += hv.z * pv.w;
            acc[3][0] += hv.w * pv.x; acc[3][1] += hv.w * pv.y;
            acc[3][2] += hv.w * pv.z; acc[3][3] += hv.w * pv.w;
        }
        __syncthreads();
    }

    // reduce denominator l across ty groups
#pragma unroll
    for (int qq = 0; qq < 4; qq++) red[ty * 64 + tx * 4 + qq] = lloc[qq];
    __syncthreads();
    if (t < 64) {
        float s = 0.f;
        for (int r = 0; r < 16; r++) s += red[r * 64 + t];
        l_sh[t] = s;
    }
    __syncthreads();

    float gam = gamma[0];
    float linv[4];
#pragma unroll
    for (int qq = 0; qq < 4; qq++) linv[qq] = 1.f / l_sh[tx * 4 + qq];

#pragma unroll
    for (int cc = 0; cc < 4; cc++) {
        int c = ty * 4 + cc;
        size_t base = ((size_t)b * CC + c) * NN + qt * 64 + tx * 4;
        float4 xin = *(const float4*)(x + base);
        float4 r;
        r.x = gam * acc[cc][0] * linv[0] + xin.x;
        r.y = gam * acc[cc][1] * linv[1] + xin.y;
        r.z = gam * acc[cc][2] * linv[2] + xin.z;
        r.w = gam * acc[cc][3] * linv[3] + xin.w;
        *(float4*)(out + base) = r;
    }
}

// ===========================================================================
extern "C" void kernel_launch(void* const* d_in, const int* in_sizes, int n_in,
                              void* d_out, int out_size) {
    const float* x     = (const float*)d_in[0];
    const float* Wq    = (const float*)d_in[1];
    const float* bq    = (const float*)d_in[2];
    const float* Wk    = (const float*)d_in[3];
    const float* bk    = (const float*)d_in[4];
    const float* Wv    = (const float*)d_in[5];
    const float* bv    = (const float*)d_in[6];
    const float* gamma = (const float*)d_in[7];
    float* out = (float*)d_out;

    prep_kernel<<<3 + (BB * NN) / 256, 256>>>(x, Wq, Wk, Wv);
    attn_kernel<<<dim3(NN / 64, BB), 256>>>(x, bq, bk, bv, gamma, out);
}

// round 8
// speedup vs baseline: 2.0131x; 1.2953x over previous
#include <cuda_runtime.h>
#include <math.h>
#include <stdint.h>

// Problem constants
#define NN 9216      // H*W = 96*96
#define CC 64        // channels
#define C8 8         // C/8
#define BB 2         // batch

// -------- scratch (static device globals: no runtime allocation) ----------
__device__ float d_invsig[3];                       // 1/sigma for Wq, Wk, Wv
__device__ float d_f[BB * NN * C8];                 // raw keys    f~ = Wq x
__device__ float d_g[BB * NN * C8];                 // raw queries g~ = Wk x
__device__ float d_h[BB * NN * CC];                 // raw values  h~ = Wv x

// ---------------- tf32 helpers -----------------
__device__ __forceinline__ uint32_t to_tf32(float x) {
    uint32_t u;
    asm("cvt.rna.tf32.f32 %0, %1;" : "=r"(u) : "f"(x));
    return u;
}
__device__ __forceinline__ void mma8(float* d,
        uint32_t a0, uint32_t a1, uint32_t a2, uint32_t a3,
        uint32_t b0, uint32_t b1) {
    asm volatile(
        "mma.sync.aligned.m16n8k8.row.col.f32.tf32.tf32.f32 "
        "{%0,%1,%2,%3},{%4,%5,%6,%7},{%8,%9},{%0,%1,%2,%3};"
        : "+f"(d[0]), "+f"(d[1]), "+f"(d[2]), "+f"(d[3])
        : "r"(a0), "r"(a1), "r"(a2), "r"(a3), "r"(b0), "r"(b1));
}

// ===========================================================================
// K1 (merged): blocks 0-2 spectral norm (squaring + short power iteration);
// blocks 3-74 raw projections. Independent halves run concurrently.
// ===========================================================================
#define SQ_ITERS 4
#define PW_ITERS 16

__global__ void __launch_bounds__(256) prep_kernel(
        const float* __restrict__ x,
        const float* __restrict__ Wq,
        const float* __restrict__ Wk,
        const float* __restrict__ Wv) {
    __shared__ float shb[8704];
    __shared__ float part[8];
    __shared__ float scal;
    int t = threadIdx.x;

    if (blockIdx.x < 3) {
        int mat = blockIdx.x;
        const float* W = (mat == 0) ? Wq : (mat == 1) ? Wk : Wv;
        int dim = (mat == 2) ? 64 : 8;
        float* Ga = shb;                 // 64*65
        float* Gb = shb + 4160;          // 64*65 (also W staging)
        float* vv = shb + 8320;          // 64

        for (int i = t; i < dim * 64; i += 256)
            Gb[(i >> 6) * 65 + (i & 63)] = W[i];
        __syncthreads();

        if (dim == 64) {
            int r = t >> 2, c0 = (t & 3) << 4;
            float rr[64];
#pragma unroll
            for (int j = 0; j < 64; j++) rr[j] = Gb[r * 65 + j];
            float acc[16];
#pragma unroll
            for (int cc = 0; cc < 16; cc++) acc[cc] = 0.f;
            for (int j = 0; j < 64; j++)
#pragma unroll
                for (int cc = 0; cc < 16; cc++)
                    acc[cc] += rr[j] * Gb[(c0 + cc) * 65 + j];
#pragma unroll
            for (int cc = 0; cc < 16; cc++) Ga[r * 65 + c0 + cc] = acc[cc];
        } else if (t < 64) {
            int r = t >> 3, c = t & 7;
            float s = 0.f;
            for (int j = 0; j < 64; j++) s += Gb[r * 65 + j] * Gb[c * 65 + j];
            Ga[r * 65 + c] = s;
        }
        __syncthreads();

        float logl = 0.f, pw = 1.f;
        float* src = Ga;
        float* dst = Gb;
        for (int it = 0; it < SQ_ITERS; it++) {
            float ss = 0.f;
            for (int e = t; e < dim * dim; e += 256) {
                float v = src[(e / dim) * 65 + (e % dim)];
                ss += v * v;
            }
#pragma unroll
            for (int o = 16; o > 0; o >>= 1)
                ss += __shfl_xor_sync(0xffffffffu, ss, o);
            if ((t & 31) == 0) part[t >> 5] = ss;
            __syncthreads();
            float tot = 0.f;
#pragma unroll
            for (int i = 0; i < 8; i++) tot += part[i];
            float fro = sqrtf(tot);
            float inv2 = 1.f / tot;
            logl += log2f(fro) * pw;
            pw *= 0.5f;

            if (dim == 64) {
                int r = t >> 2, c0 = (t & 3) << 4;
                float rr[64];
#pragma unroll
                for (int j = 0; j < 64; j++) rr[j] = src[r * 65 + j];
                float acc[16];
#pragma unroll
                for (int cc = 0; cc < 16; cc++) acc[cc] = 0.f;
                for (int j = 0; j < 64; j++)
#pragma unroll
                    for (int cc = 0; cc < 16; cc++)
                        acc[cc] += rr[j] * src[j * 65 + c0 + cc];
#pragma unroll
                for (int cc = 0; cc < 16; cc++)
                    dst[r * 65 + c0 + cc] = acc[cc] * inv2;
            } else if (t < 64) {
                int r = t >> 3, c = t & 7;
                float s = 0.f;
#pragma unroll
                for (int j = 0; j < 8; j++) s += src[r * 65 + j] * src[j * 65 + c];
                dst[r * 65 + c] = s * inv2;
            }
            __syncthreads();
            float* tmp = src; src = dst; dst = tmp;
        }

        if (t < dim) vv[t] = 1.f;
        __syncthreads();
        float lam = 1.f;
        for (int it = 0; it < PW_ITERS; it++) {
            float w = 0.f;
            if (t < dim) {
                const float* gr = src + t * 65;
                for (int j = 0; j < dim; j++) w += gr[j] * vv[j];
            }
            float sq = w * w;
#pragma unroll
            for (int o = 16; o > 0; o >>= 1)
                sq += __shfl_xor_sync(0xffffffffu, sq, o);
            if ((t & 31) == 0) part[t >> 5] = sq;
            __syncthreads();
            if (t == 0) scal = sqrtf(part[0] + part[1]);
            __syncthreads();
            lam = scal;
            if (t < dim) vv[t] = w / lam;
            __syncthreads();
        }
        if (t == 0) {
            float l0 = log2f(lam) * pw + logl;
            d_invsig[mat] = exp2f(-0.5f * l0);
        }
    } else {
        float* wq = shb;            // 512
        float* wk = shb + 512;      // 512
        float* wv = shb + 1024;     // 4096

        for (int i = t; i < 512; i += 256) { wq[i] = Wq[i]; wk[i] = Wk[i]; }
        for (int i = t; i < 4096; i += 256) wv[i] = Wv[i];
        __syncthreads();

        int gid = (blockIdx.x - 3) * 256 + t;       // 0 .. 18431
        int b = gid / NN, n = gid % NN;

        float fa[8] = {0.f}, ga[8] = {0.f}, ha[64] = {0.f};
        const float* xp = x + (size_t)b * CC * NN + n;
        for (int c = 0; c < 64; c++) {
            float xc = xp[(size_t)c * NN];
#pragma unroll
            for (int o = 0; o < 8; o++) {
                fa[o] += wq[o * 64 + c] * xc;
                ga[o] += wk[o * 64 + c] * xc;
            }
#pragma unroll
            for (int o = 0; o < 64; o++) ha[o] += wv[o * 64 + c] * xc;
        }

        size_t b8 = ((size_t)b * NN + n) * 8;
#pragma unroll
        for (int o = 0; o < 8; o++) { d_f[b8 + o] = fa[o]; d_g[b8 + o] = ga[o]; }
        size_t b64 = ((size_t)b * NN + n) * 64;
#pragma unroll
        for (int o = 0; o < 64; o++) d_h[b64 + o] = ha[o];
    }
}

// ===========================================================================
// K2: two-pass attention; PV GEMM on tensor cores (tf32 mma, 2-term split).
//   Pass 1: exact max via direct-L2 f sweep (SIMT).
//   Pass 2: per 32-key tile: stage f + H(hi/lo tf32) -> SIMT scores+exp
//           (P hi/lo tf32 to smem) -> mma.sync m16n8k8: O += Hhi*Phi +
//           Hhi*Plo + Hlo*Phi (error ~2^-22).
//   Epilogue: out = gamma * O / l + x from mma fragments.
// 256 threads = 8 warps. Warp w: c-rows [16*(w&3),+16), q-cols [32*(w>>2),+32).
// ===========================================================================
#define KT 32              // key-tile
#define HP 72              // padded row pitch for [k][*] tiles

__global__ void __launch_bounds__(256, 2) attn_kernel(
        const float* __restrict__ x,
        const float* __restrict__ bq,
        const float* __restrict__ bk,
        const float* __restrict__ bv,
        const float* __restrict__ gamma,
        float* __restrict__ out) {
    __shared__ __align__(16) float h_hi[KT * HP];   // [k][c] tf32 hi
    __shared__ __align__(16) float h_lo[KT * HP];   // [k][c] tf32 lo
    __shared__ __align__(16) float p_hi[KT * HP];   // [k][q] tf32 hi
    __shared__ __align__(16) float p_lo[KT * HP];   // [k][q] tf32 lo
    __shared__ float f_sh[KT * 9];                  // [k][d], padded
    __shared__ float g_sh[64 * 9];                  // [q][d], padded
    __shared__ float red[16 * 64];
    __shared__ float m_sh[64];
    __shared__ float l_sh[64];

    int t  = threadIdx.x;
    int tx = t & 15;        // query group (scores phase)
    int ty = t >> 4;        // key group   (scores phase)
    int b  = blockIdx.y;
    int qt = blockIdx.x;

    float iq = d_invsig[0], ik = d_invsig[1], iv = d_invsig[2];

    // stage g tile once (fully scaled + bias)
    const float* gp = d_g + ((size_t)b * NN + qt * 64) * 8;
    for (int i = t; i < 512; i += 256)
        g_sh[(i >> 3) * 9 + (i & 7)] = ik * gp[i] + __ldg(bk + (i & 7));
    __syncthreads();

    // 4 query vectors + bq-dot constants (for pass-1 algebra)
    float gq[4][8], cq[4];
#pragma unroll
    for (int qq = 0; qq < 4; qq++) {
        float c = 0.f;
#pragma unroll
        for (int d = 0; d < 8; d++) {
            gq[qq][d] = g_sh[(tx * 4 + qq) * 9 + d];
            c += __ldg(bq + d) * gq[qq][d];
        }
        cq[qq] = c;
    }

    // ---------------- pass 1: exact max, raw f straight from L2 ----------
    float mloc[4] = {-1e30f, -1e30f, -1e30f, -1e30f};
    {
        const float4* fb = (const float4*)(d_f + (size_t)b * NN * 8);
        for (int k = ty * 2; k < NN; k += 32) {
            float4 a0 = __ldg(fb + k * 2);
            float4 a1 = __ldg(fb + k * 2 + 1);
            float4 a2 = __ldg(fb + k * 2 + 2);
            float4 a3 = __ldg(fb + k * 2 + 3);
#pragma unroll
            for (int qq = 0; qq < 4; qq++) {
                float s0 = a0.x * gq[qq][0] + a0.y * gq[qq][1]
                         + a0.z * gq[qq][2] + a0.w * gq[qq][3]
                         + a1.x * gq[qq][4] + a1.y * gq[qq][5]
                         + a1.z * gq[qq][6] + a1.w * gq[qq][7];
                float s1 = a2.x * gq[qq][0] + a2.y * gq[qq][1]
                         + a2.z * gq[qq][2] + a2.w * gq[qq][3]
                         + a3.x * gq[qq][4] + a3.y * gq[qq][5]
                         + a3.z * gq[qq][6] + a3.w * gq[qq][7];
                mloc[qq] = fmaxf(mloc[qq],
                                 fmaxf(iq * s0 + cq[qq], iq * s1 + cq[qq]));
            }
        }
    }
#pragma unroll
    for (int qq = 0; qq < 4; qq++) red[ty * 64 + tx * 4 + qq] = mloc[qq];
    __syncthreads();
    if (t < 64) {
        float mm = -1e30f;
        for (int r = 0; r < 16; r++) mm = fmaxf(mm, red[r * 64 + t]);
        m_sh[t] = mm;
    }
    __syncthreads();
    float mq[4];
#pragma unroll
    for (int qq = 0; qq < 4; qq++) mq[qq] = m_sh[tx * 4 + qq];

    // ---------------- pass 2: exp + tensor-core PV + denominator ----------
    float acc[4][4];            // [n-tile j][frag reg]
#pragma unroll
    for (int i = 0; i < 4; i++)
#pragma unroll
        for (int j = 0; j < 4; j++) acc[i][j] = 0.f;
    float lloc[4] = {0.f, 0.f, 0.f, 0.f};

    const float4* bv4 = (const float4*)bv;
    int wid = t >> 5, lane = t & 31;
    int cbase = 16 * (wid & 3);
    int qbase = 32 * (wid >> 2);

    for (int kt = 0; kt < NN / KT; kt++) {
        const float* fp = d_f + ((size_t)b * NN + kt * KT) * 8;
        const float* hp = d_h + ((size_t)b * NN + kt * KT) * 64;

        // stage f (scaled+bias): 256 floats
        f_sh[(t >> 3) * 9 + (t & 7)] = iq * fp[t] + __ldg(bq + (t & 7));
        // stage H hi/lo: [k][c] pitch HP; 512 float4s
#pragma unroll
        for (int v = 0; v < 2; v++) {
            int fi = t + 256 * v;
            int k = fi >> 4, c = (fi & 15) * 4;
            float4 hv = ((const float4*)hp)[fi];
            float4 bb = bv4[fi & 15];
            float v0 = iv * hv.x + bb.x;
            float v1 = iv * hv.y + bb.y;
            float v2 = iv * hv.z + bb.z;
            float v3 = iv * hv.w + bb.w;
            float4 hi4, lo4;
            hi4.x = __uint_as_float(to_tf32(v0)); lo4.x = __uint_as_float(to_tf32(v0 - hi4.x));
            hi4.y = __uint_as_float(to_tf32(v1)); lo4.y = __uint_as_float(to_tf32(v1 - hi4.y));
            hi4.z = __uint_as_float(to_tf32(v2)); lo4.z = __uint_as_float(to_tf32(v2 - hi4.z));
            hi4.w = __uint_as_float(to_tf32(v3)); lo4.w = __uint_as_float(to_tf32(v3 - hi4.w));
            *(float4*)(h_hi + k * HP + c) = hi4;
            *(float4*)(h_lo + k * HP + c) = lo4;
        }
        __syncthreads();

        // SIMT scores + exp -> P hi/lo (each thread: 2 keys x 4 queries)
#pragma unroll
        for (int kk = 0; kk < 2; kk++) {
            int k = ty * 2 + kk;
            float fk[8];
#pragma unroll
            for (int d = 0; d < 8; d++) fk[d] = f_sh[k * 9 + d];
#pragma unroll
            for (int qq = 0; qq < 4; qq++) {
                float s = 0.f;
#pragma unroll
                for (int d = 0; d < 8; d++) s += fk[d] * gq[qq][d];
                float p = __expf(s - mq[qq]);
                lloc[qq] += p;
                float phi = __uint_as_float(to_tf32(p));
                p_hi[k * HP + tx * 4 + qq] = phi;
                p_lo[k * HP + tx * 4 + qq] = __uint_as_float(to_tf32(p - phi));
            }
        }
        __syncthreads();

        // tensor-core O += H @ P   (m=c 16, n=q 8, k=8 steps)
#pragma unroll
        for (int ks = 0; ks < KT / 8; ks++) {
            int k0 = ks * 8;
            int ar = lane >> 2, ac = lane & 3;
            uint32_t ah0 = __float_as_uint(h_hi[(k0 + ac) * HP + cbase + ar]);
            uint32_t ah1 = __float_as_uint(h_hi[(k0 + ac) * HP + cbase + ar + 8]);
            uint32_t ah2 = __float_as_uint(h_hi[(k0 + ac + 4) * HP + cbase + ar]);
            uint32_t ah3 = __float_as_uint(h_hi[(k0 + ac + 4) * HP + cbase + ar + 8]);
            uint32_t al0 = __float_as_uint(h_lo[(k0 + ac) * HP + cbase + ar]);
            uint32_t al1 = __float_as_uint(h_lo[(k0 + ac) * HP + cbase + ar + 8]);
            uint32_t al2 = __float_as_uint(h_lo[(k0 + ac + 4) * HP + cbase + ar]);
            uint32_t al3 = __float_as_uint(h_lo[(k0 + ac + 4) * HP + cbase + ar + 8]);
#pragma unroll
            for (int j = 0; j < 4; j++) {
                int qn = qbase + 8 * j + (lane >> 2);
                int kb = k0 + (lane & 3);
                uint32_t bh0 = __float_as_uint(p_hi[kb * HP + qn]);
                uint32_t bh1 = __float_as_uint(p_hi[(kb + 4) * HP + qn]);
                uint32_t bl0 = __float_as_uint(p_lo[kb * HP + qn]);
                uint32_t bl1 = __float_as_uint(p_lo[(kb + 4) * HP + qn]);
                mma8(acc[j], ah0, ah1, ah2, ah3, bh0, bh1);
                mma8(acc[j], ah0, ah1, ah2, ah3, bl0, bl1);
                mma8(acc[j], al0, al1, al2, al3, bh0, bh1);
            }
        }
        __syncthreads();
    }

    // reduce denominator l across ty groups -> store 1/l
#pragma unroll
    for (int qq = 0; qq < 4; qq++) red[ty * 64 + tx * 4 + qq] = lloc[qq];
    __syncthreads();
    if (t < 64) {
        float s = 0.f;
        for (int r = 0; r < 16; r++) s += red[r * 64 + t];
        l_sh[t] = 1.f / s;
    }
    __syncthreads();

    float gam = gamma[0];
    int row = lane >> 2, colp = (lane & 3) * 2;

#pragma unroll
    for (int j = 0; j < 4; j++) {
        int q0 = qbase + 8 * j + colp;
        float li0 = l_sh[q0], li1 = l_sh[q0 + 1];
        int c0 = cbase + row;
        size_t base0 = ((size_t)b * CC + c0) * NN + qt * 64 + q0;
        float2 x0 = *(const float2*)(x + base0);
        float2 r0;
        r0.x = gam * acc[j][0] * li0 + x0.x;
        r0.y = gam * acc[j][1] * li1 + x0.y;
        *(float2*)(out + base0) = r0;

        int c1 = c0 + 8;
        size_t base1 = ((size_t)b * CC + c1) * NN + qt * 64 + q0;
        float2 x1 = *(const float2*)(x + base1);
        float2 r1;
        r1.x = gam * acc[j][2] * li0 + x1.x;
        r1.y = gam * acc[j][3] * li1 + x1.y;
        *(float2*)(out + base1) = r1;
    }
}

// ===========================================================================
extern "C" void kernel_launch(void* const* d_in, const int* in_sizes, int n_in,
                              void* d_out, int out_size) {
    const float* x     = (const float*)d_in[0];
    const float* Wq    = (const float*)d_in[1];
    const float* bq    = (const float*)d_in[2];
    const float* Wk    = (const float*)d_in[3];
    const float* bk    = (const float*)d_in[4];
    const float* Wv    = (const float*)d_in[5];
    const float* bv    = (const float*)d_in[6];
    const float* gamma = (const float*)d_in[7];
    float* out = (float*)d_out;

    prep_kernel<<<3 + (BB * NN) / 256, 256>>>(x, Wq, Wk, Wv);
    attn_kernel<<<dim3(NN / 64, BB), 256>>>(x, bq, bk, bv, gamma, out);
}